// round 4
// baseline (speedup 1.0000x reference)
#include <cuda_runtime.h>
#include <cuda_bf16.h>

// Problem constants
#define BSZ   1024
#define TLEN  512
#define NX    32
#define NU    8
#define HN    64
#define G4    256        // 4*H
#define HB    8          // batch rows per recurrent CTA
#define NCTA  (BSZ / HB) // 128 recurrent CTAs
#define RTHR  128        // threads per recurrent CTA (2 gate rows each)

// 512 MB scratch for hoisted layer-0 input projection, layout [T][B][4H]
__device__ float g_xproj[(size_t)TLEN * BSZ * G4];

// ---------------------------------------------------------------------------
// helpers: packed f32x2 math (Blackwell-only FFMA2 via PTX)
// ---------------------------------------------------------------------------
__device__ __forceinline__ unsigned long long pack2(float lo, float hi) {
    unsigned long long r;
    asm("mov.b64 %0, {%1, %2};" : "=l"(r) : "f"(lo), "f"(hi));
    return r;
}
__device__ __forceinline__ unsigned long long pack_dup(float v) {
    unsigned long long r;
    asm("mov.b64 %0, {%1, %1};" : "=l"(r) : "f"(v));
    return r;
}
__device__ __forceinline__ void fma2(unsigned long long& d,
                                     unsigned long long a,
                                     unsigned long long b) {
    asm("fma.rn.f32x2 %0, %1, %2, %0;" : "+l"(d) : "l"(a), "l"(b));
}
__device__ __forceinline__ float2 unpack2(unsigned long long v) {
    float2 f;
    asm("mov.b64 {%0, %1}, %2;" : "=f"(f.x), "=f"(f.y) : "l"(v));
    return f;
}
__device__ __forceinline__ float getc(const float4& v, int i) {
    return (i == 0) ? v.x : (i == 1) ? v.y : (i == 2) ? v.z : v.w;
}

__device__ __forceinline__ float sig_f(float x) {
    return __fdividef(1.0f, 1.0f + __expf(-x));
}
__device__ __forceinline__ float tanh_f(float x) {
    return 1.0f - __fdividef(2.0f, __expf(2.0f * x) + 1.0f);
}

// ---------------------------------------------------------------------------
// Kernel 1: layer-0 input projection GEMM
// xproj[t][b][g] = sum_d seq[b][t][d] * W_ih0[g][d] + b_ih0[g] + b_hh0[g]
// CTA: 256 threads, 64 batch rows at fixed t. grid = T * (B/64) = 8192
// f32x2: even-d in lo lane, odd-d in hi lane; operands adjacent in memory ->
// direct 64-bit loads, zero pack instructions; one horizontal add per output.
// ---------------------------------------------------------------------------
__global__ void __launch_bounds__(256) xproj_kernel(
    const float* __restrict__ x, const float* __restrict__ u,
    const float* __restrict__ Wih0, const float* __restrict__ bih0,
    const float* __restrict__ bhh0)
{
    const int cta = blockIdx.x;
    const int t  = cta >> 4;          // cta / 16
    const int b0 = (cta & 15) << 6;   // 64-row batch block

    __shared__ float sseq[64][40];    // row stride 160 B (16B aligned)
    const int tid = threadIdx.x;

    for (int idx = tid; idx < 64 * 32; idx += 256) {
        int r = idx >> 5, i = idx & 31;
        sseq[r][i] = x[(size_t)(b0 + r) * (TLEN * NX) + t * NX + i];
    }
    for (int idx = tid; idx < 64 * 8; idx += 256) {
        int r = idx >> 3, i = idx & 7;
        sseq[r][32 + i] = u[(size_t)(b0 + r) * (TLEN * NU) + t * NU + i];
    }

    const int j = tid;
    const unsigned long long* wrow =
        (const unsigned long long*)(Wih0 + (size_t)j * 40);
    unsigned long long wd[20];
#pragma unroll
    for (int q = 0; q < 20; q++) wd[q] = wrow[q];
    const float bias = __ldg(&bih0[j]) + __ldg(&bhh0[j]);

    __syncthreads();

    float* outp = &g_xproj[(size_t)t * (BSZ * G4) + (size_t)b0 * G4 + j];
#pragma unroll 2
    for (int r = 0; r < 64; r++) {
        const ulonglong2* s2 = (const ulonglong2*)sseq[r];
        unsigned long long acc = pack2(bias, 0.0f);
#pragma unroll
        for (int q = 0; q < 10; q++) {
            ulonglong2 v = s2[q];
            fma2(acc, v.x, wd[2 * q + 0]);
            fma2(acc, v.y, wd[2 * q + 1]);
        }
        float2 f = unpack2(acc);
        outp[(size_t)r * G4] = f.x + f.y;   // coalesced over j
    }
}

// ---------------------------------------------------------------------------
// Dual-row matvec over 16 k-chunks: for rows (j0, j1):
//   acc[0..3] += h * W[j0][k],  acc[4..7] += h * W[j1][k]
// wpan layout: [kk][row j][k&3] float4; h layout: [k][8 batches]
// ---------------------------------------------------------------------------
__device__ __forceinline__ void mv16(const float4* __restrict__ wpan,
                                     const float* __restrict__ hbf,
                                     int j0, int j1,
                                     unsigned long long acc[8])
{
#pragma unroll 4
    for (int kk = 0; kk < 16; kk++) {
        float4 w0 = wpan[kk * 256 + j0];
        float4 w1 = wpan[kk * 256 + j1];
        const ulonglong2* hp = (const ulonglong2*)(hbf + kk * 32);
#pragma unroll
        for (int i = 0; i < 4; i++) {
            ulonglong2 hA = hp[2 * i + 0];  // k fixed, batches {0,1},{2,3}
            ulonglong2 hB = hp[2 * i + 1];  // batches {4,5},{6,7}
            unsigned long long p0 = pack_dup(getc(w0, i));
            unsigned long long p1 = pack_dup(getc(w1, i));
            fma2(acc[0], hA.x, p0); fma2(acc[1], hA.y, p0);
            fma2(acc[2], hB.x, p0); fma2(acc[3], hB.y, p0);
            fma2(acc[4], hA.x, p1); fma2(acc[5], hA.y, p1);
            fma2(acc[6], hB.x, p1); fma2(acc[7], hB.y, p1);
        }
    }
}

// Fused seg3: two dual-row matvecs (C1 += h1@Wih1, A = h1@Whh0) sharing the
// h1 broadcasts. Doubles fma2 per h-load phase.
__device__ __forceinline__ void mv16_fused(const float4* __restrict__ wpA,
                                           const float4* __restrict__ wpC,
                                           const float* __restrict__ hbf,
                                           int j0, int j1,
                                           unsigned long long accA[8],
                                           unsigned long long accC[8])
{
#pragma unroll 4
    for (int kk = 0; kk < 16; kk++) {
        float4 a0 = wpA[kk * 256 + j0];
        float4 a1 = wpA[kk * 256 + j1];
        float4 c0 = wpC[kk * 256 + j0];
        float4 c1 = wpC[kk * 256 + j1];
        const ulonglong2* hp = (const ulonglong2*)(hbf + kk * 32);
#pragma unroll
        for (int i = 0; i < 4; i++) {
            ulonglong2 hA = hp[2 * i + 0];
            ulonglong2 hB = hp[2 * i + 1];
            unsigned long long pa0 = pack_dup(getc(a0, i));
            unsigned long long pa1 = pack_dup(getc(a1, i));
            unsigned long long pc0 = pack_dup(getc(c0, i));
            unsigned long long pc1 = pack_dup(getc(c1, i));
            fma2(accA[0], hA.x, pa0); fma2(accA[1], hA.y, pa0);
            fma2(accA[2], hB.x, pa0); fma2(accA[3], hB.y, pa0);
            fma2(accA[4], hA.x, pa1); fma2(accA[5], hA.y, pa1);
            fma2(accA[6], hB.x, pa1); fma2(accA[7], hB.y, pa1);
            fma2(accC[0], hA.x, pc0); fma2(accC[1], hA.y, pc0);
            fma2(accC[2], hB.x, pc0); fma2(accC[3], hB.y, pc0);
            fma2(accC[4], hA.x, pc1); fma2(accC[5], hA.y, pc1);
            fma2(accC[6], hB.x, pc1); fma2(accC[7], hB.y, pc1);
        }
    }
}

// activations for rows j0 (always sigmoid: j0 in [0,128) = i,f gates) and
// j1 = j0+128 (tanh if j1<192 i.e. gate g, else sigmoid: gate o).
// Branch is warp-uniform (64-wide gate blocks).
__device__ __forceinline__ void activate2(const unsigned long long acc[8],
                                          int j0, int j1,
                                          float* __restrict__ gact)
{
    float a[8], b[8];
    {
        float2 q0 = unpack2(acc[0]), q1 = unpack2(acc[1]);
        float2 q2 = unpack2(acc[2]), q3 = unpack2(acc[3]);
        a[0]=q0.x; a[1]=q0.y; a[2]=q1.x; a[3]=q1.y;
        a[4]=q2.x; a[5]=q2.y; a[6]=q3.x; a[7]=q3.y;
        float2 r0 = unpack2(acc[4]), r1 = unpack2(acc[5]);
        float2 r2 = unpack2(acc[6]), r3 = unpack2(acc[7]);
        b[0]=r0.x; b[1]=r0.y; b[2]=r1.x; b[3]=r1.y;
        b[4]=r2.x; b[5]=r2.y; b[6]=r3.x; b[7]=r3.y;
    }
#pragma unroll
    for (int q = 0; q < 8; q++) a[q] = sig_f(a[q]);
    if (j1 < 192) {
#pragma unroll
        for (int q = 0; q < 8; q++) b[q] = tanh_f(b[q]);
    } else {
#pragma unroll
        for (int q = 0; q < 8; q++) b[q] = sig_f(b[q]);
    }
    *(float4*)(gact + j0 * 8)     = make_float4(a[0], a[1], a[2], a[3]);
    *(float4*)(gact + j0 * 8 + 4) = make_float4(a[4], a[5], a[6], a[7]);
    *(float4*)(gact + j1 * 8)     = make_float4(b[0], b[1], b[2], b[3]);
    *(float4*)(gact + j1 * 8 + 4) = make_float4(b[4], b[5], b[6], b[7]);
}

// ---------------------------------------------------------------------------
// Kernel 2: persistent 2-layer LSTM recurrence + final FC
// grid = 128 CTAs x 128 threads; CTA r owns batches [8r, 8r+8)
// thread owns gate rows j0=tid, j1=tid+128.
// Pipelined per-step schedule (accA for step t computed in prior iteration):
//   seg1: prefetch xp(t+1); C2: accC = b1 + h2(t-1)@Whh1; act0(accA)->gact
//   sync
//   seg2: c1/h1(t) update -> hbf1
//   sync
//   seg3: fused: accC += h1(t)@Wih1  AND  accA' = xp(t+1) + h1(t)@Whh0
//         act1(accC)->gact
//   sync
//   seg4: c2/h2(t) update -> hbf2
//   sync
// ---------------------------------------------------------------------------
extern __shared__ float smem_dyn[];

__global__ void __launch_bounds__(RTHR, 1) lstm_recur_kernel(
    const float* __restrict__ Whh0,
    const float* __restrict__ Wih1, const float* __restrict__ Whh1,
    const float* __restrict__ bih1, const float* __restrict__ bhh1,
    const float* __restrict__ Wfc,  const float* __restrict__ bfc,
    float* __restrict__ out)
{
    // dynamic smem layout (floats):
    float* wp0  = smem_dyn;                 // 16*256*4 = 16384 (Whh0 panels)
    float* wp1  = wp0 + 16384;              // 32*256*4 = 32768 (Wih1 | Whh1)
    float* hbf  = wp1 + 32768;              // 128*8    = 1024 (h1 | h2)
    float* gact = hbf + 1024;               // 256*8    = 2048
    float* b1s  = gact + 2048;              // 256
    // total 52480 floats = 209920 B

    const int tid = threadIdx.x;
    const int j0  = tid;          // gate row in [0,128)   (i,f gates)
    const int j1  = tid + 128;    // gate row in [128,256) (g,o gates)
    const int b0  = blockIdx.x * HB;

    // ---- stage weights into k-panel layout: wp[kk][j][k&3] = W[j][k] ----
    for (int idx = tid; idx < 256 * 64; idx += RTHR) {
        int jj = idx >> 6, k = idx & 63;
        wp0[((k >> 2) * 256 + jj) * 4 + (k & 3)] = Whh0[idx];
        wp1[((k >> 2) * 256 + jj) * 4 + (k & 3)] = Wih1[idx];
        int k2 = k + 64;
        wp1[((k2 >> 2) * 256 + jj) * 4 + (k2 & 3)] = Whh1[idx];
    }
    b1s[j0] = bih1[j0] + bhh1[j0];
    b1s[j1] = bih1[j1] + bhh1[j1];
    for (int idx = tid; idx < 1024; idx += RTHR) hbf[idx] = 0.0f;
    __syncthreads();

    const float4* wp0f4 = (const float4*)wp0;
    const float4* wp1f4 = (const float4*)wp1;   // chunks 0..15: Wih1, 16..31: Whh1
    float* hbf1 = hbf;
    float* hbf2 = hbf + 512;

    // cell state: two (float2) pairs per layer, flat pair bases p0=2*tid, p1=2*tid+256
    const int p0 = 2 * tid, p1 = 2 * tid + 256;
    float2 c1a = {0.f, 0.f}, c1b = {0.f, 0.f};
    float2 c2a = {0.f, 0.f}, c2b = {0.f, 0.f};

    // prologue: accA(0) = gates0(0) pre-activation = xproj(t=0)  (h1(-1)=0)
    unsigned long long accA[8];
    {
        const float* xq = &g_xproj[(size_t)b0 * G4];
#pragma unroll
        for (int bb = 0; bb < 4; bb++) {
            accA[bb]     = pack2(__ldg(xq + (2*bb) * G4 + j0), __ldg(xq + (2*bb+1) * G4 + j0));
            accA[4 + bb] = pack2(__ldg(xq + (2*bb) * G4 + j1), __ldg(xq + (2*bb+1) * G4 + j1));
        }
    }

#pragma unroll 1
    for (int t = 0; t < TLEN; t++) {
        // ---- seg1 ----
        // prefetch next step's xproj (consumed in seg3; DRAM latency hidden)
        int tn = t + 1; if (tn == TLEN) tn = 0;
        float xpn0[8], xpn1[8];
        {
            const float* xq = &g_xproj[(size_t)tn * (BSZ * G4) + (size_t)b0 * G4];
#pragma unroll
            for (int bb = 0; bb < HB; bb++) {
                xpn0[bb] = __ldg(xq + (size_t)bb * G4 + j0);
                xpn1[bb] = __ldg(xq + (size_t)bb * G4 + j1);
            }
        }
        // C2: accC = b1 + h2(t-1) @ Whh1^T
        unsigned long long accC[8];
        {
            unsigned long long u0 = pack_dup(b1s[j0]);
            unsigned long long u1 = pack_dup(b1s[j1]);
            accC[0]=u0; accC[1]=u0; accC[2]=u0; accC[3]=u0;
            accC[4]=u1; accC[5]=u1; accC[6]=u1; accC[7]=u1;
        }
        mv16(wp1f4 + 16 * 256, hbf2, j0, j1, accC);
        // act0 on accA (MUFU overlapped with C2's fma stream)
        activate2(accA, j0, j1, gact);
        __syncthreads();

        // ---- seg2: c1/h1 update ----
        {
            float2 gi = *(const float2*)(gact + p0);
            float2 gf = *(const float2*)(gact + 512 + p0);
            float2 gg = *(const float2*)(gact + 1024 + p0);
            float2 go = *(const float2*)(gact + 1536 + p0);
            c1a.x = gf.x * c1a.x + gi.x * gg.x;
            c1a.y = gf.y * c1a.y + gi.y * gg.y;
            float2 h; h.x = go.x * tanh_f(c1a.x); h.y = go.y * tanh_f(c1a.y);
            *(float2*)(hbf1 + p0) = h;
        }
        {
            float2 gi = *(const float2*)(gact + p1);
            float2 gf = *(const float2*)(gact + 512 + p1);
            float2 gg = *(const float2*)(gact + 1024 + p1);
            float2 go = *(const float2*)(gact + 1536 + p1);
            c1b.x = gf.x * c1b.x + gi.x * gg.x;
            c1b.y = gf.y * c1b.y + gi.y * gg.y;
            float2 h; h.x = go.x * tanh_f(c1b.x); h.y = go.y * tanh_f(c1b.y);
            *(float2*)(hbf1 + p1) = h;
        }
        __syncthreads();

        // ---- seg3: fused C1 (+= h1@Wih1) and A(t+1) (= xp + h1@Whh0) ----
#pragma unroll
        for (int bb = 0; bb < 4; bb++) {
            accA[bb]     = pack2(xpn0[2*bb], xpn0[2*bb+1]);
            accA[4 + bb] = pack2(xpn1[2*bb], xpn1[2*bb+1]);
        }
        mv16_fused(wp0f4, wp1f4, hbf1, j0, j1, accA, accC);
        // act1 on accC (MUFU overlapped with the fused fma stream)
        activate2(accC, j0, j1, gact);
        __syncthreads();

        // ---- seg4: c2/h2 update ----
        {
            float2 gi = *(const float2*)(gact + p0);
            float2 gf = *(const float2*)(gact + 512 + p0);
            float2 gg = *(const float2*)(gact + 1024 + p0);
            float2 go = *(const float2*)(gact + 1536 + p0);
            c2a.x = gf.x * c2a.x + gi.x * gg.x;
            c2a.y = gf.y * c2a.y + gi.y * gg.y;
            float2 h; h.x = go.x * tanh_f(c2a.x); h.y = go.y * tanh_f(c2a.y);
            *(float2*)(hbf2 + p0) = h;
        }
        {
            float2 gi = *(const float2*)(gact + p1);
            float2 gf = *(const float2*)(gact + 512 + p1);
            float2 gg = *(const float2*)(gact + 1024 + p1);
            float2 go = *(const float2*)(gact + 1536 + p1);
            c2b.x = gf.x * c2b.x + gi.x * gg.x;
            c2b.y = gf.y * c2b.y + gi.y * gg.y;
            float2 h; h.x = go.x * tanh_f(c2b.x); h.y = go.y * tanh_f(c2b.y);
            *(float2*)(hbf2 + p1) = h;
        }
        __syncthreads();
    }

    // ---- final FC: out[b][n] = b_fc[n] + sum_k h2[b][k] * W_fc[n][k] ----
#pragma unroll
    for (int s = 0; s < 2; s++) {
        int o = tid + s * 128;          // 256 outputs
        int b = o >> 5, n = o & 31;
        float acc = __ldg(&bfc[n]);
#pragma unroll
        for (int k = 0; k < HN; k++)
            acc = fmaf(hbf2[k * 8 + b], __ldg(&Wfc[n * HN + k]), acc);
        out[(b0 + b) * NX + n] = acc;
    }
}

// ---------------------------------------------------------------------------
extern "C" void kernel_launch(void* const* d_in, const int* in_sizes, int n_in,
                              void* d_out, int out_size)
{
    const float* x_seq = (const float*)d_in[0];
    const float* u_seq = (const float*)d_in[1];
    const float* Wih0  = (const float*)d_in[2];
    const float* Whh0  = (const float*)d_in[3];
    const float* bih0  = (const float*)d_in[4];
    const float* bhh0  = (const float*)d_in[5];
    const float* Wih1  = (const float*)d_in[6];
    const float* Whh1  = (const float*)d_in[7];
    const float* bih1  = (const float*)d_in[8];
    const float* bhh1  = (const float*)d_in[9];
    const float* Wfc   = (const float*)d_in[10];
    const float* bfc   = (const float*)d_in[11];
    float* out = (float*)d_out;

    const int SMEM_BYTES = 52480 * 4;  // 209920
    cudaFuncSetAttribute(lstm_recur_kernel,
                         cudaFuncAttributeMaxDynamicSharedMemorySize, SMEM_BYTES);

    xproj_kernel<<<TLEN * (BSZ / 64), 256>>>(x_seq, u_seq, Wih0, bih0, bhh0);
    lstm_recur_kernel<<<NCTA, RTHR, SMEM_BYTES>>>(Whh0, Wih1, Whh1, bih1, bhh1,
                                                  Wfc, bfc, out);
}